// round 11
// baseline (speedup 1.0000x reference)
#include <cuda_runtime.h>
#include <cuda_fp16.h>
#include <cstdint>

// Problem constants
#define N_ROWS   32768
#define D_DIM    512
#define C_BOOKS  64
#define K_CODES  16
#define M_OUT    128
#define NODES    15

// Scratch
__device__ __align__(16) uint32_t g_codes[N_ROWS * 8];               // 4-bit codes
__device__ __align__(16) __half   g_Lf16[M_OUT * C_BOOKS * K_CODES]; // L fp16 [m][1024]

// ---------------------------------------------------------------------------
// PTX helpers (sm_103 baseline — harness ptxas targets sm_103, no tcgen05)
// ---------------------------------------------------------------------------
__device__ __forceinline__ uint32_t smem_u32(const void* p) {
    uint32_t a;
    asm("{ .reg .u64 t; cvta.to.shared.u64 t, %1; cvt.u32.u64 %0, t; }" : "=r"(a) : "l"(p));
    return a;
}
__device__ __forceinline__ void cp16(uint32_t dst, const void* src) {
    asm volatile("cp.async.cg.shared.global [%0], [%1], 16;" :: "r"(dst), "l"(src) : "memory");
}
#define CP_COMMIT() asm volatile("cp.async.commit_group;" ::: "memory")
#define CP_WAIT(n)  asm volatile("cp.async.wait_group %0;" :: "n"(n) : "memory")

__device__ __forceinline__ void ldsm4(uint32_t& r0, uint32_t& r1, uint32_t& r2,
                                      uint32_t& r3, uint32_t addr) {
    asm volatile("ldmatrix.sync.aligned.m8n8.x4.shared.b16 {%0,%1,%2,%3}, [%4];"
                 : "=r"(r0), "=r"(r1), "=r"(r2), "=r"(r3) : "r"(addr));
}
__device__ __forceinline__ void mma16816(float* c, uint32_t a0, uint32_t a1,
                                         uint32_t a2, uint32_t a3,
                                         uint32_t b0, uint32_t b1) {
    asm volatile("mma.sync.aligned.m16n8k16.row.col.f32.f16.f16.f32 "
                 "{%0,%1,%2,%3}, {%4,%5,%6,%7}, {%8,%9}, {%0,%1,%2,%3};"
                 : "+f"(c[0]), "+f"(c[1]), "+f"(c[2]), "+f"(c[3])
                 : "r"(a0), "r"(a1), "r"(a2), "r"(a3), "r"(b0), "r"(b1));
}

// ---------------------------------------------------------------------------
// Kernel 1: encode (16 rows/CTA, 256 threads) + fused L->fp16 convert.
// ---------------------------------------------------------------------------
#define ENC_ROWS    16
#define ENC_THREADS 256
#define ROW_PAD     516

__global__ __launch_bounds__(ENC_THREADS)
void encode_kernel(const float* __restrict__ I,
                   const float* __restrict__ T,
                   const int*   __restrict__ dims,
                   const float* __restrict__ L)
{
    extern __shared__ float sm[];
    float* Ir = sm;
    float* Ts = sm + ENC_ROWS * ROW_PAD;
    int*   ds = (int*)(Ts + 960);

    const int tid = threadIdx.x;
    const int nb  = blockIdx.x * ENC_ROWS;
    const uint32_t sbase = smem_u32(sm);

    // cp.async staging of 16 rows (2048 x 16B)
    const char* src = (const char*)(I + (size_t)nb * D_DIM);
    #pragma unroll
    for (int i = 0; i < 8; i++) {
        int q = tid + ENC_THREADS * i;
        int r = q >> 7;
        int j = q & 127;
        cp16(sbase + (uint32_t)(r * (ROW_PAD * 4) + j * 16),
             src + (size_t)r * (D_DIM * 4) + j * 16);
    }
    CP_COMMIT();

    // Fused convert: first 128 CTAs each convert 256 float4 of L -> g_Lf16
    if (blockIdx.x < 128) {
        int q = blockIdx.x * 256 + tid;
        float4 v = ((const float4*)L)[q];
        ((__half2*)g_Lf16)[q * 2]     = __floats2half2_rn(v.x, v.y);
        ((__half2*)g_Lf16)[q * 2 + 1] = __floats2half2_rn(v.z, v.w);
    }

    for (int i = tid; i < 960; i += ENC_THREADS) Ts[i] = T[i];
    ds[tid] = dims[tid];

    CP_WAIT(0);
    __syncthreads();

    const int r  = tid >> 4;
    const int cg = tid & 15;
    const float* row = Ir + r * ROW_PAD;

    uint32_t pack = 0;
    #pragma unroll
    for (int j = 0; j < 4; j++) {
        const int c = cg * 4 + j;
        const int*   dp = ds + c * 4;
        const float* tp = Ts + c * NODES;
        const float v0 = row[dp[0]];
        const float v1 = row[dp[1]];
        const float v2 = row[dp[2]];
        const float v3 = row[dp[3]];
        int p;
        p = (v0 > tp[0]) ? 1 : 0;
        p = (p << 1) | ((v1 > tp[1 + p]) ? 1 : 0);
        p = (p << 1) | ((v2 > tp[3 + p]) ? 1 : 0);
        p = (p << 1) | ((v3 > tp[7 + p]) ? 1 : 0);
        pack |= ((uint32_t)p) << (4 * j);
    }
    ((uint16_t*)g_codes)[(size_t)(nb + r) * 16 + cg] = (uint16_t)pack;
}

// ---------------------------------------------------------------------------
// Kernel 2: tensor aggregation (mma.sync m16n8k16).
// Tile: 128n x 64m per CTA, grid (256, 2). 8 warps as 4(n) x 2(m):
// warp = 32n x 32m -> acc[2][4][4] = 32 regs (high occupancy) AND each
// ldsm.x4 pair feeds 16 MMAs (low LDSM traffic) — combines r7 reuse with
// r10 occupancy. 3 CTAs/SM = 24 warps.
// B chunk (64m x 128k fp16) double-buffered via cp.async, 1 sync/chunk.
// ---------------------------------------------------------------------------
#define AGG_THREADS 256
#define NTILE       128
#define MTILE       64
#define BROW        272                         // 256B data + 16B pad per m-row
#define BTILE_B     (MTILE * BROW)              // 17408
#define SM_BUF      4096
#define SM_AGG      (SM_BUF + 2 * BTILE_B)      // 38912 -> 3 CTAs/SM

__global__ __launch_bounds__(AGG_THREADS, 3)
void agg_kernel(float* __restrict__ out)
{
    extern __shared__ __align__(16) char smem[];
    const uint32_t sb = smem_u32(smem);
    const int tid  = threadIdx.x;
    const int wid  = tid >> 5;
    const int lane = tid & 31;
    const int g    = lane >> 2;     // 0..7
    const int tg   = lane & 3;      // 0..3
    const int n0   = blockIdx.x * NTILE;
    const int mg0  = blockIdx.y * MTILE;

    // Stage codes: 128 rows * 32B = 256 uint4
    {
        const uint4* srcc = (const uint4*)(g_codes + (size_t)n0 * 8);
        ((uint4*)smem)[tid] = srcc[tid];
    }

    // ldmatrix per-lane constant offset (validated layout)
    const int t = lane >> 3;
    const uint32_t lane_m   = (uint32_t)(((t >> 1) * 8) + (lane & 7));
    const uint32_t lane_off = lane_m * BROW + (uint32_t)((t & 1) * 16);

    const int rbase = (wid & 3) * 32;    // warp rows within CTA (32 each)
    const int mwarp = (wid >> 2) * 32;   // warp m within CTA (32 each)

    // stage chunk 'c' (64 m x 128 k) into buffer buf
    const char* srcL = (const char*)g_Lf16 + (size_t)mg0 * 2048;
    #define STAGE(c, buf)                                                        \
        do {                                                                     \
            const uint32_t bdst = sb + SM_BUF + (buf) * BTILE_B;                 \
            const char* s = srcL + (c) * 256;                                    \
            _Pragma("unroll")                                                    \
            for (int i = 0; i < 4; i++) {                                        \
                int q = tid + AGG_THREADS * i;                                   \
                int m = q >> 4, seg = q & 15;                                    \
                cp16(bdst + (uint32_t)(m * BROW + seg * 16),                     \
                     s + (size_t)m * 2048 + seg * 16);                           \
            }                                                                    \
            CP_COMMIT();                                                         \
        } while (0)

    STAGE(0, 0);

    float acc[2][4][4];
    #pragma unroll
    for (int rt = 0; rt < 2; rt++)
        #pragma unroll
        for (int nb = 0; nb < 4; nb++)
            #pragma unroll
            for (int i = 0; i < 4; i++) acc[rt][nb][i] = 0.f;

    const uint32_t* cs = (const uint32_t*)smem;

    #pragma unroll 1
    for (int ch = 0; ch < 8; ch++) {
        CP_WAIT(0);
        __syncthreads();
        if (ch < 7) { STAGE(ch + 1, (ch + 1) & 1); }   // overlaps with consume

        const uint32_t bbase = sb + SM_BUF + (ch & 1) * BTILE_B
                             + (uint32_t)mwarp * BROW + lane_off;

        // code words: 2 row-tiles x (row g, row g+8)
        uint32_t wlo[2], whi[2];
        #pragma unroll
        for (int rt = 0; rt < 2; rt++) {
            wlo[rt] = cs[(rbase + 16 * rt + g)     * 8 + ch];
            whi[rt] = cs[(rbase + 16 * rt + g + 8) * 8 + ch];
        }

        #pragma unroll
        for (int kbl = 0; kbl < 8; kbl++) {
            // B fragments: 32 m = two 16-m ldmatrix.x4 (feeds 16 MMAs)
            uint32_t b[2][4];
            #pragma unroll
            for (int p = 0; p < 2; p++) {
                ldsm4(b[p][0], b[p][1], b[p][2], b[p][3],
                      bbase + (uint32_t)(kbl * 32) + (uint32_t)(p * 16 * BROW));
            }
            #pragma unroll
            for (int rt = 0; rt < 2; rt++) {
                const uint32_t klo = (wlo[rt] >> (4 * kbl)) & 15u;
                const uint32_t khi = (whi[rt] >> (4 * kbl)) & 15u;
                const uint32_t hlo = 0x3C00u << ((klo & 1u) << 4);
                const uint32_t hhi = 0x3C00u << ((khi & 1u) << 4);
                const uint32_t slo = klo >> 1, shi = khi >> 1;
                const uint32_t A0 = (slo == (uint32_t)tg)     ? hlo : 0u;
                const uint32_t A1 = (shi == (uint32_t)tg)     ? hhi : 0u;
                const uint32_t A2 = (slo == (uint32_t)tg + 4) ? hlo : 0u;
                const uint32_t A3 = (shi == (uint32_t)tg + 4) ? hhi : 0u;
                #pragma unroll
                for (int p = 0; p < 2; p++) {
                    mma16816(acc[rt][2 * p],     A0, A1, A2, A3, b[p][0], b[p][1]);
                    mma16816(acc[rt][2 * p + 1], A0, A1, A2, A3, b[p][2], b[p][3]);
                }
            }
        }
    }

    // Epilogue: STG.64 pairs
    #pragma unroll
    for (int rt = 0; rt < 2; rt++) {
        const int rowA = n0 + rbase + 16 * rt + g;
        #pragma unroll
        for (int nb = 0; nb < 4; nb++) {
            float2 lo = make_float2(acc[rt][nb][0], acc[rt][nb][1]);
            float2 hi = make_float2(acc[rt][nb][2], acc[rt][nb][3]);
            *(float2*)(out + (size_t)rowA * M_OUT + mg0 + mwarp + nb * 8 + tg * 2)       = lo;
            *(float2*)(out + (size_t)(rowA + 8) * M_OUT + mg0 + mwarp + nb * 8 + tg * 2) = hi;
        }
    }
    #undef STAGE
}

// ---------------------------------------------------------------------------
extern "C" void kernel_launch(void* const* d_in, const int* in_sizes, int n_in,
                              void* d_out, int out_size)
{
    (void)in_sizes; (void)n_in; (void)out_size;
    const float* I    = (const float*)d_in[0];
    const float* T    = (const float*)d_in[1];
    const float* L    = (const float*)d_in[2];
    const int*   dims = (const int*)d_in[5];
    float* out = (float*)d_out;

    const int encSmem = (ENC_ROWS * ROW_PAD + 960 + 256) * 4;  // 37888
    cudaFuncSetAttribute(encode_kernel, cudaFuncAttributeMaxDynamicSharedMemorySize, encSmem);
    cudaFuncSetAttribute(agg_kernel,    cudaFuncAttributeMaxDynamicSharedMemorySize, SM_AGG);

    encode_kernel<<<N_ROWS / ENC_ROWS, ENC_THREADS, encSmem>>>(I, T, dims, L);
    agg_kernel<<<dim3(N_ROWS / NTILE, M_OUT / MTILE), AGG_THREADS, SM_AGG>>>(out);
}

// round 12
// speedup vs baseline: 1.0276x; 1.0276x over previous
#include <cuda_runtime.h>
#include <cuda_fp16.h>
#include <cstdint>

// Problem constants
#define N_ROWS   32768
#define D_DIM    512
#define C_BOOKS  64
#define K_CODES  16
#define M_OUT    128
#define NODES    15

// Scratch
__device__ __align__(16) uint32_t g_codes[N_ROWS * 8];               // 4-bit codes
__device__ __align__(16) __half   g_Lf16[M_OUT * C_BOOKS * K_CODES]; // L fp16 [m][1024]

// ---------------------------------------------------------------------------
// PTX helpers (sm_103 baseline — harness ptxas targets sm_103, no tcgen05)
// ---------------------------------------------------------------------------
__device__ __forceinline__ uint32_t smem_u32(const void* p) {
    uint32_t a;
    asm("{ .reg .u64 t; cvta.to.shared.u64 t, %1; cvt.u32.u64 %0, t; }" : "=r"(a) : "l"(p));
    return a;
}
__device__ __forceinline__ void cp16(uint32_t dst, const void* src) {
    asm volatile("cp.async.cg.shared.global [%0], [%1], 16;" :: "r"(dst), "l"(src) : "memory");
}
#define CP_COMMIT() asm volatile("cp.async.commit_group;" ::: "memory")
#define CP_WAIT(n)  asm volatile("cp.async.wait_group %0;" :: "n"(n) : "memory")
#define STS128(addr, a, b, c, d) \
    asm volatile("st.shared.v4.b32 [%0], {%1,%2,%3,%4};" \
                 :: "r"(addr), "r"(a), "r"(b), "r"(c), "r"(d) : "memory")

__device__ __forceinline__ void ldsm4(uint32_t& r0, uint32_t& r1, uint32_t& r2,
                                      uint32_t& r3, uint32_t addr) {
    asm volatile("ldmatrix.sync.aligned.m8n8.x4.shared.b16 {%0,%1,%2,%3}, [%4];"
                 : "=r"(r0), "=r"(r1), "=r"(r2), "=r"(r3) : "r"(addr));
}
__device__ __forceinline__ void mma16816(float* c, uint32_t a0, uint32_t a1,
                                         uint32_t a2, uint32_t a3,
                                         uint32_t b0, uint32_t b1) {
    asm volatile("mma.sync.aligned.m16n8k16.row.col.f32.f16.f16.f32 "
                 "{%0,%1,%2,%3}, {%4,%5,%6,%7}, {%8,%9}, {%0,%1,%2,%3};"
                 : "+f"(c[0]), "+f"(c[1]), "+f"(c[2]), "+f"(c[3])
                 : "r"(a0), "r"(a1), "r"(a2), "r"(a3), "r"(b0), "r"(b1));
}

// ---------------------------------------------------------------------------
// Kernel 1: encode (16 rows/CTA, 256 threads) + fused L->fp16 convert.
// ---------------------------------------------------------------------------
#define ENC_ROWS    16
#define ENC_THREADS 256
#define ROW_PAD     516

__global__ __launch_bounds__(ENC_THREADS)
void encode_kernel(const float* __restrict__ I,
                   const float* __restrict__ T,
                   const int*   __restrict__ dims,
                   const float* __restrict__ L)
{
    extern __shared__ float sm[];
    float* Ir = sm;
    float* Ts = sm + ENC_ROWS * ROW_PAD;
    int*   ds = (int*)(Ts + 960);

    const int tid = threadIdx.x;
    const int nb  = blockIdx.x * ENC_ROWS;
    const uint32_t sbase = smem_u32(sm);

    const char* src = (const char*)(I + (size_t)nb * D_DIM);
    #pragma unroll
    for (int i = 0; i < 8; i++) {
        int q = tid + ENC_THREADS * i;
        int r = q >> 7;
        int j = q & 127;
        cp16(sbase + (uint32_t)(r * (ROW_PAD * 4) + j * 16),
             src + (size_t)r * (D_DIM * 4) + j * 16);
    }
    CP_COMMIT();

    if (blockIdx.x < 128) {
        int q = blockIdx.x * 256 + tid;
        float4 v = ((const float4*)L)[q];
        ((__half2*)g_Lf16)[q * 2]     = __floats2half2_rn(v.x, v.y);
        ((__half2*)g_Lf16)[q * 2 + 1] = __floats2half2_rn(v.z, v.w);
    }

    for (int i = tid; i < 960; i += ENC_THREADS) Ts[i] = T[i];
    ds[tid] = dims[tid];

    CP_WAIT(0);
    __syncthreads();

    const int r  = tid >> 4;
    const int cg = tid & 15;
    const float* row = Ir + r * ROW_PAD;

    uint32_t pack = 0;
    #pragma unroll
    for (int j = 0; j < 4; j++) {
        const int c = cg * 4 + j;
        const int*   dp = ds + c * 4;
        const float* tp = Ts + c * NODES;
        const float v0 = row[dp[0]];
        const float v1 = row[dp[1]];
        const float v2 = row[dp[2]];
        const float v3 = row[dp[3]];
        int p;
        p = (v0 > tp[0]) ? 1 : 0;
        p = (p << 1) | ((v1 > tp[1 + p]) ? 1 : 0);
        p = (p << 1) | ((v2 > tp[3 + p]) ? 1 : 0);
        p = (p << 1) | ((v3 > tp[7 + p]) ? 1 : 0);
        pack |= ((uint32_t)p) << (4 * j);
    }
    ((uint16_t*)g_codes)[(size_t)(nb + r) * 16 + cg] = (uint16_t)pack;
}

// ---------------------------------------------------------------------------
// Kernel 2: tensor aggregation. A (one-hot) built in SMEM per 64-k chunk
// (cheap cooperative STS.128 from codes), then ldmatrix'd like B — removes
// per-warp register synthesis ALU and its register pressure.
// CTA 128n x 128m, 8 warps as 4(n) x 2(m), warp = 32n x 64m, acc=64 regs.
// A and B double-buffered (B via cp.async), 64-k chunks x 16, 1 sync/chunk.
// ---------------------------------------------------------------------------
#define AGG_THREADS 256
#define NTILE       128
#define TROW        144                         // 128B data + 16B pad per row
#define ATILE_B     (128 * TROW)                // 18432 (128 n-rows)
#define BTILE_B     (128 * TROW)                // 18432 (128 m-rows)
#define SM_CODES    0                           // 4096
#define SM_A        4096                        // 2 x 18432
#define SM_B        (SM_A + 2 * ATILE_B)        // 40960
#define SM_AGG      (SM_B + 2 * BTILE_B)        // 77824 -> 2 CTAs/SM

__global__ __launch_bounds__(AGG_THREADS, 2)
void agg_kernel(float* __restrict__ out)
{
    extern __shared__ __align__(16) char smem[];
    const uint32_t sb = smem_u32(smem);
    const int tid  = threadIdx.x;
    const int wid  = tid >> 5;
    const int lane = tid & 31;
    const int g    = lane >> 2;
    const int tg   = lane & 3;
    const int n0   = blockIdx.x * NTILE;

    // Stage codes: 128 rows * 32B = 256 uint4
    {
        const uint4* srcc = (const uint4*)(g_codes + (size_t)n0 * 8);
        ((uint4*)smem)[tid] = srcc[tid];
    }
    __syncthreads();          // codes visible for A builds

    const uint32_t* cs = (const uint32_t*)smem;

    // ---- per-lane ldmatrix offsets (row stride TROW=144B, conflict-free) ----
    // A (16n x 16k per ldsm.x4): lanes 0-15 -> rows, lanes 16-31 -> +16B (k+8)
    const uint32_t a_lane = (uint32_t)((lane & 15) * TROW + (lane >> 4) * 16);
    // B (16m x 16k per ldsm.x4): r7-validated pattern
    const int t = lane >> 3;
    const uint32_t b_lane = (uint32_t)((((t >> 1) * 8) + (lane & 7)) * TROW
                                       + (t & 1) * 16);

    const int rbase = (wid & 3) * 32;    // warp rows (32 each)
    const int mwarp = (wid >> 2) * 64;   // warp m (64 each)

    // ---- B staging: chunk = 128 m x 64 k halves (8 x 16B per row) ----
    const char* srcL = (const char*)g_Lf16;
    #define STAGE(c, buf)                                                        \
        do {                                                                     \
            const uint32_t bdst = sb + SM_B + (buf) * BTILE_B;                   \
            const char* s = srcL + (c) * 128;                                    \
            _Pragma("unroll")                                                    \
            for (int i = 0; i < 4; i++) {                                        \
                int q = tid + AGG_THREADS * i;                                   \
                int m = q >> 3, seg = q & 7;                                     \
                cp16(bdst + (uint32_t)(m * TROW + seg * 16),                     \
                     s + (size_t)m * 2048 + seg * 16);                           \
            }                                                                    \
            CP_COMMIT();                                                         \
        } while (0)

    // ---- A build: chunk ch covers codebooks ch*4 .. ch*4+3 ----
    // thread -> (n = tid>>1, 2 codebook-units); unit = 16 halves (32B).
    const int an   = tid >> 1;
    const int acb2 = (tid & 1) * 2;
    #define BUILDA(ch, buf)                                                      \
        do {                                                                     \
            const uint32_t adst = sb + SM_A + (buf) * ATILE_B                    \
                                + (uint32_t)(an * TROW + acb2 * 32);             \
            const uint32_t wrd = cs[an * 8 + ((ch) >> 1)];                       \
            _Pragma("unroll")                                                    \
            for (int u = 0; u < 2; u++) {                                        \
                const int c = (ch) * 4 + acb2 + u;                               \
                const uint32_t code = (wrd >> ((c & 7) * 4)) & 15u;              \
                const uint32_t wsel = code >> 1;                                 \
                const uint32_t val  = 0x3C00u << ((code & 1u) << 4);             \
                uint32_t r0 = (wsel == 0) ? val : 0u;                            \
                uint32_t r1 = (wsel == 1) ? val : 0u;                            \
                uint32_t r2 = (wsel == 2) ? val : 0u;                            \
                uint32_t r3 = (wsel == 3) ? val : 0u;                            \
                uint32_t r4 = (wsel == 4) ? val : 0u;                            \
                uint32_t r5 = (wsel == 5) ? val : 0u;                            \
                uint32_t r6 = (wsel == 6) ? val : 0u;                            \
                uint32_t r7 = (wsel == 7) ? val : 0u;                            \
                STS128(adst + u * 32,      r0, r1, r2, r3);                      \
                STS128(adst + u * 32 + 16, r4, r5, r6, r7);                      \
            }                                                                    \
        } while (0)

    STAGE(0, 0);
    BUILDA(0, 0);

    float acc[2][8][4];
    #pragma unroll
    for (int rt = 0; rt < 2; rt++)
        #pragma unroll
        for (int nb = 0; nb < 8; nb++)
            #pragma unroll
            for (int i = 0; i < 4; i++) acc[rt][nb][i] = 0.f;

    #pragma unroll 1
    for (int ch = 0; ch < 16; ch++) {
        CP_WAIT(0);
        __syncthreads();     // B[ch] arrived; A[ch] built; prev MMA done
        if (ch < 15) {
            STAGE(ch + 1, (ch + 1) & 1);
            BUILDA(ch + 1, (ch + 1) & 1);
        }

        const uint32_t ab = sb + SM_A + (ch & 1) * ATILE_B
                          + (uint32_t)(rbase * TROW) + a_lane;
        const uint32_t bb = sb + SM_B + (ch & 1) * BTILE_B
                          + (uint32_t)(mwarp * TROW) + b_lane;

        #pragma unroll
        for (int kbl = 0; kbl < 4; kbl++) {
            const uint32_t ko = (uint32_t)(kbl * 32);
            uint32_t a[2][4];
            #pragma unroll
            for (int rt = 0; rt < 2; rt++) {
                ldsm4(a[rt][0], a[rt][1], a[rt][2], a[rt][3],
                      ab + ko + (uint32_t)(rt * 16 * TROW));
            }
            uint32_t b[4][4];
            #pragma unroll
            for (int p = 0; p < 4; p++) {
                ldsm4(b[p][0], b[p][1], b[p][2], b[p][3],
                      bb + ko + (uint32_t)(p * 16 * TROW));
            }
            #pragma unroll
            for (int rt = 0; rt < 2; rt++) {
                #pragma unroll
                for (int p = 0; p < 4; p++) {
                    mma16816(acc[rt][2 * p],     a[rt][0], a[rt][1], a[rt][2],
                             a[rt][3], b[p][0], b[p][1]);
                    mma16816(acc[rt][2 * p + 1], a[rt][0], a[rt][1], a[rt][2],
                             a[rt][3], b[p][2], b[p][3]);
                }
            }
        }
    }

    // Epilogue: STG.64 pairs
    #pragma unroll
    for (int rt = 0; rt < 2; rt++) {
        const int rowA = n0 + rbase + 16 * rt + g;
        #pragma unroll
        for (int nb = 0; nb < 8; nb++) {
            float2 lo = make_float2(acc[rt][nb][0], acc[rt][nb][1]);
            float2 hi = make_float2(acc[rt][nb][2], acc[rt][nb][3]);
            *(float2*)(out + (size_t)rowA * M_OUT + mwarp + nb * 8 + tg * 2)       = lo;
            *(float2*)(out + (size_t)(rowA + 8) * M_OUT + mwarp + nb * 8 + tg * 2) = hi;
        }
    }
    #undef STAGE
    #undef BUILDA
}

// ---------------------------------------------------------------------------
extern "C" void kernel_launch(void* const* d_in, const int* in_sizes, int n_in,
                              void* d_out, int out_size)
{
    (void)in_sizes; (void)n_in; (void)out_size;
    const float* I    = (const float*)d_in[0];
    const float* T    = (const float*)d_in[1];
    const float* L    = (const float*)d_in[2];
    const int*   dims = (const int*)d_in[5];
    float* out = (float*)d_out;

    const int encSmem = (ENC_ROWS * ROW_PAD + 960 + 256) * 4;  // 37888
    cudaFuncSetAttribute(encode_kernel, cudaFuncAttributeMaxDynamicSharedMemorySize, encSmem);
    cudaFuncSetAttribute(agg_kernel,    cudaFuncAttributeMaxDynamicSharedMemorySize, SM_AGG);

    encode_kernel<<<N_ROWS / ENC_ROWS, ENC_THREADS, encSmem>>>(I, T, dims, L);
    agg_kernel<<<N_ROWS / NTILE, AGG_THREADS, SM_AGG>>>(out);
}

// round 13
// speedup vs baseline: 1.0396x; 1.0117x over previous
#include <cuda_runtime.h>
#include <cuda_fp16.h>
#include <cstdint>

// Problem constants
#define N_ROWS   32768
#define D_DIM    512
#define C_BOOKS  64
#define K_CODES  16
#define M_OUT    128
#define NODES    15

// Scratch
__device__ __align__(16) uint32_t g_codes[N_ROWS * 8];               // 4-bit codes
__device__ __align__(16) __half   g_Lf16[M_OUT * C_BOOKS * K_CODES]; // L fp16 [m][1024]

// ---------------------------------------------------------------------------
// PTX helpers (sm_103 baseline — harness ptxas targets sm_103, no tcgen05)
// ---------------------------------------------------------------------------
__device__ __forceinline__ uint32_t smem_u32(const void* p) {
    uint32_t a;
    asm("{ .reg .u64 t; cvta.to.shared.u64 t, %1; cvt.u32.u64 %0, t; }" : "=r"(a) : "l"(p));
    return a;
}
__device__ __forceinline__ void cp16(uint32_t dst, const void* src) {
    asm volatile("cp.async.cg.shared.global [%0], [%1], 16;" :: "r"(dst), "l"(src) : "memory");
}
#define CP_COMMIT() asm volatile("cp.async.commit_group;" ::: "memory")
#define CP_WAIT(n)  asm volatile("cp.async.wait_group %0;" :: "n"(n) : "memory")

__device__ __forceinline__ void ldsm4(uint32_t& r0, uint32_t& r1, uint32_t& r2,
                                      uint32_t& r3, uint32_t addr) {
    asm volatile("ldmatrix.sync.aligned.m8n8.x4.shared.b16 {%0,%1,%2,%3}, [%4];"
                 : "=r"(r0), "=r"(r1), "=r"(r2), "=r"(r3) : "r"(addr));
}
__device__ __forceinline__ void mma16816(float* c, uint32_t a0, uint32_t a1,
                                         uint32_t a2, uint32_t a3,
                                         uint32_t b0, uint32_t b1) {
    asm volatile("mma.sync.aligned.m16n8k16.row.col.f32.f16.f16.f32 "
                 "{%0,%1,%2,%3}, {%4,%5,%6,%7}, {%8,%9}, {%0,%1,%2,%3};"
                 : "+f"(c[0]), "+f"(c[1]), "+f"(c[2]), "+f"(c[3])
                 : "r"(a0), "r"(a1), "r"(a2), "r"(a3), "r"(b0), "r"(b1));
}

// ---------------------------------------------------------------------------
// Kernel 1: encode (16 rows/CTA, 256 threads) + fused L->fp16 convert.
// ---------------------------------------------------------------------------
#define ENC_ROWS    16
#define ENC_THREADS 256
#define ROW_PAD     516

__global__ __launch_bounds__(ENC_THREADS)
void encode_kernel(const float* __restrict__ I,
                   const float* __restrict__ T,
                   const int*   __restrict__ dims,
                   const float* __restrict__ L)
{
    extern __shared__ float sm[];
    float* Ir = sm;
    float* Ts = sm + ENC_ROWS * ROW_PAD;
    int*   ds = (int*)(Ts + 960);

    const int tid = threadIdx.x;
    const int nb  = blockIdx.x * ENC_ROWS;
    const uint32_t sbase = smem_u32(sm);

    const char* src = (const char*)(I + (size_t)nb * D_DIM);
    #pragma unroll
    for (int i = 0; i < 8; i++) {
        int q = tid + ENC_THREADS * i;
        int r = q >> 7;
        int j = q & 127;
        cp16(sbase + (uint32_t)(r * (ROW_PAD * 4) + j * 16),
             src + (size_t)r * (D_DIM * 4) + j * 16);
    }
    CP_COMMIT();

    if (blockIdx.x < 128) {
        int q = blockIdx.x * 256 + tid;
        float4 v = ((const float4*)L)[q];
        ((__half2*)g_Lf16)[q * 2]     = __floats2half2_rn(v.x, v.y);
        ((__half2*)g_Lf16)[q * 2 + 1] = __floats2half2_rn(v.z, v.w);
    }

    for (int i = tid; i < 960; i += ENC_THREADS) Ts[i] = T[i];
    ds[tid] = dims[tid];

    CP_WAIT(0);
    __syncthreads();

    const int r  = tid >> 4;
    const int cg = tid & 15;
    const float* row = Ir + r * ROW_PAD;

    uint32_t pack = 0;
    #pragma unroll
    for (int j = 0; j < 4; j++) {
        const int c = cg * 4 + j;
        const int*   dp = ds + c * 4;
        const float* tp = Ts + c * NODES;
        const float v0 = row[dp[0]];
        const float v1 = row[dp[1]];
        const float v2 = row[dp[2]];
        const float v3 = row[dp[3]];
        int p;
        p = (v0 > tp[0]) ? 1 : 0;
        p = (p << 1) | ((v1 > tp[1 + p]) ? 1 : 0);
        p = (p << 1) | ((v2 > tp[3 + p]) ? 1 : 0);
        p = (p << 1) | ((v3 > tp[7 + p]) ? 1 : 0);
        pack |= ((uint32_t)p) << (4 * j);
    }
    ((uint16_t*)g_codes)[(size_t)(nb + r) * 16 + cg] = (uint16_t)pack;
}

// ---------------------------------------------------------------------------
// Kernel 2: tensor aggregation (mma.sync m16n8k16) — r10 layout pushed to
// 4 CTAs/SM. Tile 128n x 64m per CTA, grid (256, 2). 8 warps of 16n x 64m.
// acc[8][4]=32 regs; B fragments staged as two ldsm pairs (8 live frag regs)
// to fit the 64-reg budget of __launch_bounds__(256,4) -> 32 warps/SM.
// B chunk (64m x 128k fp16) double-buffered via cp.async, 1 sync/chunk.
// ---------------------------------------------------------------------------
#define AGG_THREADS 256
#define NTILE       128
#define MTILE       64
#define BROW        272                         // 256B data + 16B pad per m-row
#define BTILE_B     (MTILE * BROW)              // 17408
#define SM_BUF      4096
#define SM_AGG      (SM_BUF + 2 * BTILE_B)      // 38912 -> 4 CTAs/SM (155.6KB)

__global__ __launch_bounds__(AGG_THREADS, 4)
void agg_kernel(float* __restrict__ out)
{
    extern __shared__ __align__(16) char smem[];
    const uint32_t sb = smem_u32(smem);
    const int tid  = threadIdx.x;
    const int wid  = tid >> 5;
    const int lane = tid & 31;
    const int g    = lane >> 2;     // 0..7
    const int tg   = lane & 3;      // 0..3
    const int n0   = blockIdx.x * NTILE;
    const int mg0  = blockIdx.y * MTILE;

    // Stage codes: 128 rows * 32B = 256 uint4
    {
        const uint4* srcc = (const uint4*)(g_codes + (size_t)n0 * 8);
        ((uint4*)smem)[tid] = srcc[tid];
    }

    // ldmatrix per-lane constant offset (validated layout)
    const int t = lane >> 3;
    const uint32_t lane_off = (uint32_t)((((t >> 1) * 8) + (lane & 7)) * BROW
                                         + (t & 1) * 16);

    const int rbase = wid * 16;          // warp rows within CTA (16 each)

    // stage chunk 'c' (64 m x 128 k) into buffer buf
    const char* srcL = (const char*)g_Lf16 + (size_t)mg0 * 2048;
    #define STAGE(c, buf)                                                        \
        do {                                                                     \
            const uint32_t bdst = sb + SM_BUF + (buf) * BTILE_B;                 \
            const char* s = srcL + (c) * 256;                                    \
            _Pragma("unroll")                                                    \
            for (int i = 0; i < 4; i++) {                                        \
                int q = tid + AGG_THREADS * i;                                   \
                int m = q >> 4, seg = q & 15;                                    \
                cp16(bdst + (uint32_t)(m * BROW + seg * 16),                     \
                     s + (size_t)m * 2048 + seg * 16);                           \
            }                                                                    \
            CP_COMMIT();                                                         \
        } while (0)

    STAGE(0, 0);

    float acc[8][4];
    #pragma unroll
    for (int nb = 0; nb < 8; nb++)
        #pragma unroll
        for (int i = 0; i < 4; i++) acc[nb][i] = 0.f;

    const uint32_t* cs = (const uint32_t*)smem;

    #pragma unroll 1
    for (int ch = 0; ch < 8; ch++) {
        CP_WAIT(0);
        __syncthreads();
        if (ch < 7) { STAGE(ch + 1, (ch + 1) & 1); }   // overlaps with consume

        const uint32_t bbase = sb + SM_BUF + (ch & 1) * BTILE_B + lane_off;

        const uint32_t wlo = cs[(rbase + g)     * 8 + ch];
        const uint32_t whi = cs[(rbase + g + 8) * 8 + ch];

        #pragma unroll
        for (int kbl = 0; kbl < 8; kbl++) {
            // A one-hot fragments (row g from wlo, row g+8 from whi)
            const uint32_t klo = (wlo >> (4 * kbl)) & 15u;
            const uint32_t khi = (whi >> (4 * kbl)) & 15u;
            const uint32_t hlo = 0x3C00u << ((klo & 1u) << 4);
            const uint32_t hhi = 0x3C00u << ((khi & 1u) << 4);
            const uint32_t slo = klo >> 1, shi = khi >> 1;
            const uint32_t A0 = (slo == (uint32_t)tg)     ? hlo : 0u;
            const uint32_t A1 = (shi == (uint32_t)tg)     ? hhi : 0u;
            const uint32_t A2 = (slo == (uint32_t)tg + 4) ? hlo : 0u;
            const uint32_t A3 = (shi == (uint32_t)tg + 4) ? hhi : 0u;

            const uint32_t bk = bbase + (uint32_t)(kbl * 32);

            // First pair of B fragments (m 0..31) -> 4 MMAs
            {
                uint32_t b[2][4];
                ldsm4(b[0][0], b[0][1], b[0][2], b[0][3], bk);
                ldsm4(b[1][0], b[1][1], b[1][2], b[1][3],
                      bk + (uint32_t)(16 * BROW));
                mma16816(acc[0], A0, A1, A2, A3, b[0][0], b[0][1]);
                mma16816(acc[1], A0, A1, A2, A3, b[0][2], b[0][3]);
                mma16816(acc[2], A0, A1, A2, A3, b[1][0], b[1][1]);
                mma16816(acc[3], A0, A1, A2, A3, b[1][2], b[1][3]);
            }
            // Second pair (m 32..63) -> 4 MMAs
            {
                uint32_t b[2][4];
                ldsm4(b[0][0], b[0][1], b[0][2], b[0][3],
                      bk + (uint32_t)(2 * 16 * BROW));
                ldsm4(b[1][0], b[1][1], b[1][2], b[1][3],
                      bk + (uint32_t)(3 * 16 * BROW));
                mma16816(acc[4], A0, A1, A2, A3, b[0][0], b[0][1]);
                mma16816(acc[5], A0, A1, A2, A3, b[0][2], b[0][3]);
                mma16816(acc[6], A0, A1, A2, A3, b[1][0], b[1][1]);
                mma16816(acc[7], A0, A1, A2, A3, b[1][2], b[1][3]);
            }
        }
    }

    // Epilogue: STG.64 pairs
    {
        const int rowA = n0 + rbase + g;
        #pragma unroll
        for (int nb = 0; nb < 8; nb++) {
            float2 lo = make_float2(acc[nb][0], acc[nb][1]);
            float2 hi = make_float2(acc[nb][2], acc[nb][3]);
            *(float2*)(out + (size_t)rowA * M_OUT + mg0 + nb * 8 + tg * 2)       = lo;
            *(float2*)(out + (size_t)(rowA + 8) * M_OUT + mg0 + nb * 8 + tg * 2) = hi;
        }
    }
    #undef STAGE
}

// ---------------------------------------------------------------------------
extern "C" void kernel_launch(void* const* d_in, const int* in_sizes, int n_in,
                              void* d_out, int out_size)
{
    (void)in_sizes; (void)n_in; (void)out_size;
    const float* I    = (const float*)d_in[0];
    const float* T    = (const float*)d_in[1];
    const float* L    = (const float*)d_in[2];
    const int*   dims = (const int*)d_in[5];
    float* out = (float*)d_out;

    const int encSmem = (ENC_ROWS * ROW_PAD + 960 + 256) * 4;  // 37888
    cudaFuncSetAttribute(encode_kernel, cudaFuncAttributeMaxDynamicSharedMemorySize, encSmem);
    cudaFuncSetAttribute(agg_kernel,    cudaFuncAttributeMaxDynamicSharedMemorySize, SM_AGG);

    encode_kernel<<<N_ROWS / ENC_ROWS, ENC_THREADS, encSmem>>>(I, T, dims, L);
    agg_kernel<<<dim3(N_ROWS / NTILE, M_OUT / MTILE), AGG_THREADS, SM_AGG>>>(out);
}

// round 14
// speedup vs baseline: 1.1133x; 1.0709x over previous
#include <cuda_runtime.h>
#include <cuda_fp16.h>
#include <cstdint>

// Problem constants
#define N_ROWS   32768
#define D_DIM    512
#define C_BOOKS  64
#define K_CODES  16
#define M_OUT    128
#define NODES    15

// Scratch
__device__ __align__(16) uint32_t g_codes[N_ROWS * 8];               // 4-bit codes
__device__ __align__(16) __half   g_Lf16[M_OUT * C_BOOKS * K_CODES]; // L fp16 [m][1024]

// ---------------------------------------------------------------------------
// PTX helpers (sm_103 baseline — harness ptxas targets sm_103, no tcgen05)
// ---------------------------------------------------------------------------
__device__ __forceinline__ uint32_t smem_u32(const void* p) {
    uint32_t a;
    asm("{ .reg .u64 t; cvta.to.shared.u64 t, %1; cvt.u32.u64 %0, t; }" : "=r"(a) : "l"(p));
    return a;
}
__device__ __forceinline__ void cp16(uint32_t dst, const void* src) {
    asm volatile("cp.async.cg.shared.global [%0], [%1], 16;" :: "r"(dst), "l"(src) : "memory");
}
#define CP_COMMIT() asm volatile("cp.async.commit_group;" ::: "memory")
#define CP_WAIT(n)  asm volatile("cp.async.wait_group %0;" :: "n"(n) : "memory")

__device__ __forceinline__ void ldsm4(uint32_t& r0, uint32_t& r1, uint32_t& r2,
                                      uint32_t& r3, uint32_t addr) {
    asm volatile("ldmatrix.sync.aligned.m8n8.x4.shared.b16 {%0,%1,%2,%3}, [%4];"
                 : "=r"(r0), "=r"(r1), "=r"(r2), "=r"(r3) : "r"(addr));
}
__device__ __forceinline__ void mma16816(float* c, uint32_t a0, uint32_t a1,
                                         uint32_t a2, uint32_t a3,
                                         uint32_t b0, uint32_t b1) {
    asm volatile("mma.sync.aligned.m16n8k16.row.col.f32.f16.f16.f32 "
                 "{%0,%1,%2,%3}, {%4,%5,%6,%7}, {%8,%9}, {%0,%1,%2,%3};"
                 : "+f"(c[0]), "+f"(c[1]), "+f"(c[2]), "+f"(c[3])
                 : "r"(a0), "r"(a1), "r"(a2), "r"(a3), "r"(b0), "r"(b1));
}

// ---------------------------------------------------------------------------
// Kernel 1: encode (16 rows/CTA, 256 threads) + fused L->fp16 convert.
// ---------------------------------------------------------------------------
#define ENC_ROWS    16
#define ENC_THREADS 256
#define ROW_PAD     516

__global__ __launch_bounds__(ENC_THREADS)
void encode_kernel(const float* __restrict__ I,
                   const float* __restrict__ T,
                   const int*   __restrict__ dims,
                   const float* __restrict__ L)
{
    extern __shared__ float sm[];
    float* Ir = sm;
    float* Ts = sm + ENC_ROWS * ROW_PAD;
    int*   ds = (int*)(Ts + 960);

    const int tid = threadIdx.x;
    const int nb  = blockIdx.x * ENC_ROWS;
    const uint32_t sbase = smem_u32(sm);

    const char* src = (const char*)(I + (size_t)nb * D_DIM);
    #pragma unroll
    for (int i = 0; i < 8; i++) {
        int q = tid + ENC_THREADS * i;
        int r = q >> 7;
        int j = q & 127;
        cp16(sbase + (uint32_t)(r * (ROW_PAD * 4) + j * 16),
             src + (size_t)r * (D_DIM * 4) + j * 16);
    }
    CP_COMMIT();

    if (blockIdx.x < 128) {
        int q = blockIdx.x * 256 + tid;
        float4 v = ((const float4*)L)[q];
        ((__half2*)g_Lf16)[q * 2]     = __floats2half2_rn(v.x, v.y);
        ((__half2*)g_Lf16)[q * 2 + 1] = __floats2half2_rn(v.z, v.w);
    }

    for (int i = tid; i < 960; i += ENC_THREADS) Ts[i] = T[i];
    ds[tid] = dims[tid];

    CP_WAIT(0);
    __syncthreads();

    const int r  = tid >> 4;
    const int cg = tid & 15;
    const float* row = Ir + r * ROW_PAD;

    uint32_t pack = 0;
    #pragma unroll
    for (int j = 0; j < 4; j++) {
        const int c = cg * 4 + j;
        const int*   dp = ds + c * 4;
        const float* tp = Ts + c * NODES;
        const float v0 = row[dp[0]];
        const float v1 = row[dp[1]];
        const float v2 = row[dp[2]];
        const float v3 = row[dp[3]];
        int p;
        p = (v0 > tp[0]) ? 1 : 0;
        p = (p << 1) | ((v1 > tp[1 + p]) ? 1 : 0);
        p = (p << 1) | ((v2 > tp[3 + p]) ? 1 : 0);
        p = (p << 1) | ((v3 > tp[7 + p]) ? 1 : 0);
        pack |= ((uint32_t)p) << (4 * j);
    }
    ((uint16_t*)g_codes)[(size_t)(nb + r) * 16 + cg] = (uint16_t)pack;
}

// ---------------------------------------------------------------------------
// Kernel 2: tensor aggregation, BARRIER-FREE mainloop.
// CTA = 512n x 64m, 512 threads = 16 warps stacked in n; warp = 32n x 64m
// (r7's proven ALU/LDSM mix). B (64m x 1024k fp16, 129KB) + codes (16KB)
// fully SMEM-resident: stage once w/ cp.async, ONE sync, then warps free-run
// with zero synchronization -> natural de-phasing fills dependency stalls.
// Grid (64, 2) = 128 CTAs = single wave on 148 SMs.
// ---------------------------------------------------------------------------
#define AGG_THREADS 512
#define NTILE       512
#define MTILE       64
#define BROW        2064                         // 2048B data + 16B pad per m-row
#define SM_CODES    0                            // 512 rows * 32B = 16384
#define SM_B        16384
#define SM_AGG      (SM_B + MTILE * BROW)        // 16384 + 132096 = 148480

__global__ __launch_bounds__(AGG_THREADS)
void agg_kernel(float* __restrict__ out)
{
    extern __shared__ __align__(16) char smem[];
    const uint32_t sb = smem_u32(smem);
    const int tid  = threadIdx.x;
    const int wid  = tid >> 5;
    const int lane = tid & 31;
    const int g    = lane >> 2;     // 0..7
    const int tg   = lane & 3;      // 0..3
    const int n0   = blockIdx.x * NTILE;
    const int mg0  = blockIdx.y * MTILE;

    // ---- stage codes: 512 rows * 32B = 1024 x 16B ----
    {
        const char* srcc = (const char*)(g_codes + (size_t)n0 * 8);
        #pragma unroll
        for (int i = 0; i < 2; i++) {
            int q = tid + AGG_THREADS * i;
            cp16(sb + SM_CODES + (uint32_t)(q * 16), srcc + (size_t)q * 16);
        }
    }
    // ---- stage B: 64 m-rows x 128 x 16B ----
    {
        const char* srcL = (const char*)g_Lf16 + (size_t)mg0 * 2048;
        #pragma unroll
        for (int i = 0; i < 16; i++) {
            int q = tid + AGG_THREADS * i;       // 8192 total
            int m = q >> 7, seg = q & 127;
            cp16(sb + SM_B + (uint32_t)(m * BROW + seg * 16),
                 srcL + (size_t)m * 2048 + seg * 16);
        }
    }
    CP_COMMIT();
    CP_WAIT(0);
    __syncthreads();            // the ONLY barrier

    // ldmatrix per-lane constant offset (validated pattern; BROW=2064:
    // row-to-row bank shift 4 words -> 8 rows distinct banks, conflict-free)
    const int t = lane >> 3;
    const uint32_t lane_off = (uint32_t)((((t >> 1) * 8) + (lane & 7)) * BROW
                                         + (t & 1) * 16);

    const int rbase = wid * 32;          // warp rows within CTA (32 each)
    const uint32_t* cs = (const uint32_t*)smem;
    const uint32_t bwarp = sb + SM_B + lane_off;

    float acc[2][8][4];
    #pragma unroll
    for (int rt = 0; rt < 2; rt++)
        #pragma unroll
        for (int nb = 0; nb < 8; nb++)
            #pragma unroll
            for (int i = 0; i < 4; i++) acc[rt][nb][i] = 0.f;

    #pragma unroll 1
    for (int ch = 0; ch < 8; ch++) {
        const uint32_t bbase = bwarp + (uint32_t)(ch * 256);

        uint32_t wlo[2], whi[2];
        #pragma unroll
        for (int rt = 0; rt < 2; rt++) {
            wlo[rt] = cs[(rbase + 16 * rt + g)     * 8 + ch];
            whi[rt] = cs[(rbase + 16 * rt + g + 8) * 8 + ch];
        }

        #pragma unroll
        for (int kbl = 0; kbl < 8; kbl++) {
            // B fragments: 64 m = four 16-m ldmatrix.x4 (feeds 16 MMAs)
            uint32_t b[4][4];
            #pragma unroll
            for (int p = 0; p < 4; p++) {
                ldsm4(b[p][0], b[p][1], b[p][2], b[p][3],
                      bbase + (uint32_t)(kbl * 32) + (uint32_t)(p * 16 * BROW));
            }
            #pragma unroll
            for (int rt = 0; rt < 2; rt++) {
                const uint32_t klo = (wlo[rt] >> (4 * kbl)) & 15u;
                const uint32_t khi = (whi[rt] >> (4 * kbl)) & 15u;
                const uint32_t hlo = 0x3C00u << ((klo & 1u) << 4);
                const uint32_t hhi = 0x3C00u << ((khi & 1u) << 4);
                const uint32_t slo = klo >> 1, shi = khi >> 1;
                const uint32_t A0 = (slo == (uint32_t)tg)     ? hlo : 0u;
                const uint32_t A1 = (shi == (uint32_t)tg)     ? hhi : 0u;
                const uint32_t A2 = (slo == (uint32_t)tg + 4) ? hlo : 0u;
                const uint32_t A3 = (shi == (uint32_t)tg + 4) ? hhi : 0u;
                #pragma unroll
                for (int p = 0; p < 4; p++) {
                    mma16816(acc[rt][2 * p],     A0, A1, A2, A3, b[p][0], b[p][1]);
                    mma16816(acc[rt][2 * p + 1], A0, A1, A2, A3, b[p][2], b[p][3]);
                }
            }
        }
    }

    // Epilogue: STG.64 pairs
    #pragma unroll
    for (int rt = 0; rt < 2; rt++) {
        const int rowA = n0 + rbase + 16 * rt + g;
        #pragma unroll
        for (int nb = 0; nb < 8; nb++) {
            float2 lo = make_float2(acc[rt][nb][0], acc[rt][nb][1]);
            float2 hi = make_float2(acc[rt][nb][2], acc[rt][nb][3]);
            *(float2*)(out + (size_t)rowA * M_OUT + mg0 + nb * 8 + tg * 2)       = lo;
            *(float2*)(out + (size_t)(rowA + 8) * M_OUT + mg0 + nb * 8 + tg * 2) = hi;
        }
    }
}

// ---------------------------------------------------------------------------
extern "C" void kernel_launch(void* const* d_in, const int* in_sizes, int n_in,
                              void* d_out, int out_size)
{
    (void)in_sizes; (void)n_in; (void)out_size;
    const float* I    = (const float*)d_in[0];
    const float* T    = (const float*)d_in[1];
    const float* L    = (const float*)d_in[2];
    const int*   dims = (const int*)d_in[5];
    float* out = (float*)d_out;

    const int encSmem = (ENC_ROWS * ROW_PAD + 960 + 256) * 4;  // 37888
    cudaFuncSetAttribute(encode_kernel, cudaFuncAttributeMaxDynamicSharedMemorySize, encSmem);
    cudaFuncSetAttribute(agg_kernel,    cudaFuncAttributeMaxDynamicSharedMemorySize, SM_AGG);

    encode_kernel<<<N_ROWS / ENC_ROWS, ENC_THREADS, encSmem>>>(I, T, dims, L);
    agg_kernel<<<dim3(N_ROWS / NTILE, M_OUT / MTILE), AGG_THREADS, SM_AGG>>>(out);
}

// round 15
// speedup vs baseline: 1.1258x; 1.0112x over previous
#include <cuda_runtime.h>
#include <cuda_fp16.h>
#include <cstdint>

// Problem constants
#define N_ROWS   32768
#define D_DIM    512
#define C_BOOKS  64
#define K_CODES  16
#define M_OUT    128
#define NODES    15

// Scratch
__device__ __align__(16) uint32_t g_codes[N_ROWS * 8];               // 4-bit codes
__device__ __align__(16) __half   g_Lf16[M_OUT * C_BOOKS * K_CODES]; // L fp16 [m][1024]

// ---------------------------------------------------------------------------
// PTX helpers (sm_103 baseline — harness ptxas targets sm_103, no tcgen05)
// ---------------------------------------------------------------------------
__device__ __forceinline__ uint32_t smem_u32(const void* p) {
    uint32_t a;
    asm("{ .reg .u64 t; cvta.to.shared.u64 t, %1; cvt.u32.u64 %0, t; }" : "=r"(a) : "l"(p));
    return a;
}
__device__ __forceinline__ void cp16(uint32_t dst, const void* src) {
    asm volatile("cp.async.cg.shared.global [%0], [%1], 16;" :: "r"(dst), "l"(src) : "memory");
}
#define CP_COMMIT() asm volatile("cp.async.commit_group;" ::: "memory")
#define CP_WAIT(n)  asm volatile("cp.async.wait_group %0;" :: "n"(n) : "memory")

__device__ __forceinline__ void ldsm4(uint32_t& r0, uint32_t& r1, uint32_t& r2,
                                      uint32_t& r3, uint32_t addr) {
    asm volatile("ldmatrix.sync.aligned.m8n8.x4.shared.b16 {%0,%1,%2,%3}, [%4];"
                 : "=r"(r0), "=r"(r1), "=r"(r2), "=r"(r3) : "r"(addr));
}
__device__ __forceinline__ void mma16816(float* c, uint32_t a0, uint32_t a1,
                                         uint32_t a2, uint32_t a3,
                                         uint32_t b0, uint32_t b1) {
    asm volatile("mma.sync.aligned.m16n8k16.row.col.f32.f16.f16.f32 "
                 "{%0,%1,%2,%3}, {%4,%5,%6,%7}, {%8,%9}, {%0,%1,%2,%3};"
                 : "+f"(c[0]), "+f"(c[1]), "+f"(c[2]), "+f"(c[3])
                 : "r"(a0), "r"(a1), "r"(a2), "r"(a3), "r"(b0), "r"(b1));
}

// ---------------------------------------------------------------------------
// Kernel 1: encode (16 rows/CTA, 256 threads) + fused L->fp16 convert.
// ---------------------------------------------------------------------------
#define ENC_ROWS    16
#define ENC_THREADS 256
#define ROW_PAD     516

__global__ __launch_bounds__(ENC_THREADS)
void encode_kernel(const float* __restrict__ I,
                   const float* __restrict__ T,
                   const int*   __restrict__ dims,
                   const float* __restrict__ L)
{
    extern __shared__ float sm[];
    float* Ir = sm;
    float* Ts = sm + ENC_ROWS * ROW_PAD;
    int*   ds = (int*)(Ts + 960);

    const int tid = threadIdx.x;
    const int nb  = blockIdx.x * ENC_ROWS;
    const uint32_t sbase = smem_u32(sm);

    const char* src = (const char*)(I + (size_t)nb * D_DIM);
    #pragma unroll
    for (int i = 0; i < 8; i++) {
        int q = tid + ENC_THREADS * i;
        int r = q >> 7;
        int j = q & 127;
        cp16(sbase + (uint32_t)(r * (ROW_PAD * 4) + j * 16),
             src + (size_t)r * (D_DIM * 4) + j * 16);
    }
    CP_COMMIT();

    if (blockIdx.x < 128) {
        int q = blockIdx.x * 256 + tid;
        float4 v = ((const float4*)L)[q];
        ((__half2*)g_Lf16)[q * 2]     = __floats2half2_rn(v.x, v.y);
        ((__half2*)g_Lf16)[q * 2 + 1] = __floats2half2_rn(v.z, v.w);
    }

    for (int i = tid; i < 960; i += ENC_THREADS) Ts[i] = T[i];
    ds[tid] = dims[tid];

    CP_WAIT(0);
    __syncthreads();

    const int r  = tid >> 4;
    const int cg = tid & 15;
    const float* row = Ir + r * ROW_PAD;

    uint32_t pack = 0;
    #pragma unroll
    for (int j = 0; j < 4; j++) {
        const int c = cg * 4 + j;
        const int*   dp = ds + c * 4;
        const float* tp = Ts + c * NODES;
        const float v0 = row[dp[0]];
        const float v1 = row[dp[1]];
        const float v2 = row[dp[2]];
        const float v3 = row[dp[3]];
        int p;
        p = (v0 > tp[0]) ? 1 : 0;
        p = (p << 1) | ((v1 > tp[1 + p]) ? 1 : 0);
        p = (p << 1) | ((v2 > tp[3 + p]) ? 1 : 0);
        p = (p << 1) | ((v3 > tp[7 + p]) ? 1 : 0);
        pack |= ((uint32_t)p) << (4 * j);
    }
    ((uint16_t*)g_codes)[(size_t)(nb + r) * 16 + cg] = (uint16_t)pack;
}

// ---------------------------------------------------------------------------
// Kernel 2: tensor aggregation, barrier-free mainloop (r14) + SMEM A-LUT.
// A-fragment pair (A0,A2) is a function of (code nibble, tg) only: 64 uint2
// entries. Per k-block a lane does 4x {bfe, LDS.64} instead of ~28 ALU ops,
// dropping per-iter issue demand below the tensor-pipe budget.
// CTA = 512n x 64m, 512 threads; warp = 32n x 64m. B + codes SMEM-resident,
// staged once via cp.async, ONE sync, then warps free-run.
// Grid (64, 2) = 128 CTAs = single wave.
// ---------------------------------------------------------------------------
#define AGG_THREADS 512
#define NTILE       512
#define MTILE       64
#define BROW        2064                         // 2048B data + 16B pad per m-row
#define SM_CODES    0                            // 512 rows * 32B = 16384
#define SM_LUT      16384                        // 64 x uint2 = 512
#define SM_B        17408                        // 1024-aligned
#define SM_AGG      (SM_B + MTILE * BROW)        // 17408 + 132096 = 149504

__global__ __launch_bounds__(AGG_THREADS)
void agg_kernel(float* __restrict__ out)
{
    extern __shared__ __align__(16) char smem[];
    const uint32_t sb = smem_u32(smem);
    const int tid  = threadIdx.x;
    const int wid  = tid >> 5;
    const int lane = tid & 31;
    const int g    = lane >> 2;     // 0..7
    const int tg   = lane & 3;      // 0..3
    const int n0   = blockIdx.x * NTILE;
    const int mg0  = blockIdx.y * MTILE;

    // ---- stage codes: 512 rows * 32B = 1024 x 16B ----
    {
        const char* srcc = (const char*)(g_codes + (size_t)n0 * 8);
        #pragma unroll
        for (int i = 0; i < 2; i++) {
            int q = tid + AGG_THREADS * i;
            cp16(sb + SM_CODES + (uint32_t)(q * 16), srcc + (size_t)q * 16);
        }
    }
    // ---- stage B: 64 m-rows x 128 x 16B ----
    {
        const char* srcL = (const char*)g_Lf16 + (size_t)mg0 * 2048;
        #pragma unroll
        for (int i = 0; i < 16; i++) {
            int q = tid + AGG_THREADS * i;       // 8192 total
            int m = q >> 7, seg = q & 127;
            cp16(sb + SM_B + (uint32_t)(m * BROW + seg * 16),
                 srcL + (size_t)m * 2048 + seg * 16);
        }
    }
    CP_COMMIT();

    // ---- build A-fragment LUT: entry[k][t] = {A_klow, A_khigh} ----
    if (tid < 64) {
        const uint32_t k  = (uint32_t)(tid >> 2);
        const uint32_t tt = (uint32_t)(tid & 3);
        const uint32_t hv = 0x3C00u << ((k & 1u) << 4);
        const uint32_t s  = k >> 1;
        uint2 e;
        e.x = (s == tt)      ? hv : 0u;     // k in low 8 (a0/a1 slot)
        e.y = (s == tt + 4u) ? hv : 0u;     // k in high 8 (a2/a3 slot)
        ((uint2*)(smem + SM_LUT))[tid] = e;
    }

    CP_WAIT(0);
    __syncthreads();            // the ONLY barrier

    // ldmatrix per-lane constant offset (validated pattern)
    const int t = lane >> 3;
    const uint32_t lane_off = (uint32_t)((((t >> 1) * 8) + (lane & 7)) * BROW
                                         + (t & 1) * 16);

    const int rbase = wid * 32;          // warp rows within CTA (32 each)
    const uint32_t* cs = (const uint32_t*)smem;
    const uint2* LUT = (const uint2*)(smem + SM_LUT);
    const uint32_t bwarp = sb + SM_B + lane_off;

    float acc[2][8][4];
    #pragma unroll
    for (int rt = 0; rt < 2; rt++)
        #pragma unroll
        for (int nb = 0; nb < 8; nb++)
            #pragma unroll
            for (int i = 0; i < 4; i++) acc[rt][nb][i] = 0.f;

    #pragma unroll 1
    for (int ch = 0; ch < 8; ch++) {
        const uint32_t bbase = bwarp + (uint32_t)(ch * 256);

        uint32_t wlo[2], whi[2];
        #pragma unroll
        for (int rt = 0; rt < 2; rt++) {
            wlo[rt] = cs[(rbase + 16 * rt + g)     * 8 + ch];
            whi[rt] = cs[(rbase + 16 * rt + g + 8) * 8 + ch];
        }

        #pragma unroll
        for (int kbl = 0; kbl < 8; kbl++) {
            // B fragments: 64 m = four 16-m ldmatrix.x4 (feeds 16 MMAs)
            uint32_t b[4][4];
            #pragma unroll
            for (int p = 0; p < 4; p++) {
                ldsm4(b[p][0], b[p][1], b[p][2], b[p][3],
                      bbase + (uint32_t)(kbl * 32) + (uint32_t)(p * 16 * BROW));
            }
            #pragma unroll
            for (int rt = 0; rt < 2; rt++) {
                const uint32_t klo = (wlo[rt] >> (4 * kbl)) & 15u;
                const uint32_t khi = (whi[rt] >> (4 * kbl)) & 15u;
                const uint2 elo = LUT[(int)(klo * 4) + tg];   // {A0, A2}
                const uint2 ehi = LUT[(int)(khi * 4) + tg];   // {A1, A3}
                #pragma unroll
                for (int p = 0; p < 4; p++) {
                    mma16816(acc[rt][2 * p],     elo.x, ehi.x, elo.y, ehi.y,
                             b[p][0], b[p][1]);
                    mma16816(acc[rt][2 * p + 1], elo.x, ehi.x, elo.y, ehi.y,
                             b[p][2], b[p][3]);
                }
            }
        }
    }

    // Epilogue: STG.64 pairs
    #pragma unroll
    for (int rt = 0; rt < 2; rt++) {
        const int rowA = n0 + rbase + 16 * rt + g;
        #pragma unroll
        for (int nb = 0; nb < 8; nb++) {
            float2 lo = make_float2(acc[rt][nb][0], acc[rt][nb][1]);
            float2 hi = make_float2(acc[rt][nb][2], acc[rt][nb][3]);
            *(float2*)(out + (size_t)rowA * M_OUT + mg0 + nb * 8 + tg * 2)       = lo;
            *(float2*)(out + (size_t)(rowA + 8) * M_OUT + mg0 + nb * 8 + tg * 2) = hi;
        }
    }
}

// ---------------------------------------------------------------------------
extern "C" void kernel_launch(void* const* d_in, const int* in_sizes, int n_in,
                              void* d_out, int out_size)
{
    (void)in_sizes; (void)n_in; (void)out_size;
    const float* I    = (const float*)d_in[0];
    const float* T    = (const float*)d_in[1];
    const float* L    = (const float*)d_in[2];
    const int*   dims = (const int*)d_in[5];
    float* out = (float*)d_out;

    const int encSmem = (ENC_ROWS * ROW_PAD + 960 + 256) * 4;  // 37888
    cudaFuncSetAttribute(encode_kernel, cudaFuncAttributeMaxDynamicSharedMemorySize, encSmem);
    cudaFuncSetAttribute(agg_kernel,    cudaFuncAttributeMaxDynamicSharedMemorySize, SM_AGG);

    encode_kernel<<<N_ROWS / ENC_ROWS, ENC_THREADS, encSmem>>>(I, T, dims, L);
    agg_kernel<<<dim3(N_ROWS / NTILE, M_OUT / MTILE), AGG_THREADS, SM_AGG>>>(out);
}